// round 14
// baseline (speedup 1.0000x reference)
#include <cuda_runtime.h>
#include <cuda_fp16.h>
#include <cstdint>

// ============================================================================
// Upsample: out = stack_k(x @ W[k]) [8*65536,128] -> BN(train stats) -> ReLU
// fp16 mma.sync (f32 accum) at the legacy-HMMA ceiling. R14: convert || gram
// concurrency (gram reads f32 x directly + computes cs; convert PDL-triggers
// at entry), g_done guard for gemm's xh/wh reads, PSS+sync on reduce/stats.
// ============================================================================

#define MT      65536
#define KT      256
#define CO      128
#define NOFF    8
#define BM      128
#define MTILES  512
#define GSPLIT  96            // k-splits for Gram
#define GTILES  3             // symmetric 128x128 blocks: (0,0),(0,1),(1,1)
#define NCONVB  4352          // 4096 x-blocks + 256 W-blocks

// ---- device scratch ----
__device__ __align__(16) __half g_xh[(size_t)MT * KT];        // row-major
__device__ __align__(16) __half g_wh[NOFF * CO * KT];         // [k][n][kk]
__device__ float g_gp[(size_t)GTILES * GSPLIT * 128 * 128];   // Gram partials
__device__ float g_G [KT * KT];
__device__ float g_cspart[KT * GSPLIT];                       // [ch][split]
__device__ float g_cs[KT];
__device__ float g_qpart[CO * NOFF];                          // [d][k]
__device__ float g_mpart[CO * NOFF];                          // [d][k]
__device__ unsigned long long g_done;                         // convert blocks

// ---- PTX helpers ----
__device__ __forceinline__ uint32_t smem_u32(const void* p) {
    uint32_t a;
    asm("{ .reg .u64 t; cvta.to.shared.u64 t, %1; cvt.u32.u64 %0, t; }" : "=r"(a) : "l"(p));
    return a;
}
__device__ __forceinline__ void cp16(uint32_t dst, const void* src) {
    asm volatile("cp.async.cg.shared.global [%0], [%1], 16;" :: "r"(dst), "l"(src) : "memory");
}
#define CP_COMMIT() asm volatile("cp.async.commit_group;" ::: "memory")
#define CP_WAIT(n)  asm volatile("cp.async.wait_group %0;" :: "n"(n) : "memory")

__device__ __forceinline__ void ldsm4(uint32_t r[4], uint32_t a) {
    asm volatile("ldmatrix.sync.aligned.m8n8.x4.shared.b16 {%0,%1,%2,%3}, [%4];"
                 : "=r"(r[0]), "=r"(r[1]), "=r"(r[2]), "=r"(r[3]) : "r"(a));
}
__device__ __forceinline__ void ldsm4t(uint32_t r[4], uint32_t a) {
    asm volatile("ldmatrix.sync.aligned.m8n8.x4.trans.shared.b16 {%0,%1,%2,%3}, [%4];"
                 : "=r"(r[0]), "=r"(r[1]), "=r"(r[2]), "=r"(r[3]) : "r"(a));
}
__device__ __forceinline__ void mma16816(float d[4], const uint32_t a[4], const uint32_t b[2]) {
    asm volatile(
        "mma.sync.aligned.m16n8k16.row.col.f32.f16.f16.f32 "
        "{%0,%1,%2,%3}, {%4,%5,%6,%7}, {%8,%9}, {%0,%1,%2,%3};"
        : "+f"(d[0]), "+f"(d[1]), "+f"(d[2]), "+f"(d[3])
        : "r"(a[0]), "r"(a[1]), "r"(a[2]), "r"(a[3]), "r"(b[0]), "r"(b[1]));
}

// ============================================================================
// convert_all (pure streaming): x -> f16 g_xh; W -> f16 g_wh (transposed).
// Triggers PDL at entry so gram (which reads f32 x directly) overlaps fully.
// Each block release-increments g_done at exit (consumed by gemm's guard).
// ============================================================================
__global__ __launch_bounds__(256) void convert_all(const float* __restrict__ x,
                                                   const float* __restrict__ W) {
    cudaTriggerProgrammaticLaunchCompletion();
    const int b = blockIdx.x, tid = threadIdx.x;
    if (b < 4096) {
        const int bx = b >> 2, by = b & 3;
        const int r0 = bx * 64, c0 = by * 64;
        const int cl = (tid & 7) * 8;
#pragma unroll
        for (int h = 0; h < 2; h++) {
            int rl = h * 32 + (tid >> 3);
            const float* src = x + (size_t)(r0 + rl) * KT + c0 + cl;
            float4 f0 = *(const float4*)src;
            float4 f1 = *(const float4*)(src + 4);
            float v[8] = {f0.x, f0.y, f0.z, f0.w, f1.x, f1.y, f1.z, f1.w};
            __half hh[8];
#pragma unroll
            for (int j = 0; j < 8; j++) hh[j] = __float2half(v[j]);
            *(uint4*)(g_xh + (size_t)(r0 + rl) * KT + c0 + cl) = *(uint4*)hh;
        }
    } else {
        // W transpose-convert: W[k][kk][n] (f32) -> g_wh[k][n][kk] (f16)
        __shared__ float wt[32][33];
        const int t = b - 4096;          // 0..255
        const int k = t >> 5, tile = t & 31;
        const int tk = tile >> 2, tn = tile & 3;
#pragma unroll
        for (int p = 0; p < 4; p++) {
            int row = p * 8 + (tid >> 5), col = tid & 31;
            wt[row][col] = W[((size_t)(k * KT + tk * 32 + row)) * CO + tn * 32 + col];
        }
        __syncthreads();
        const int r2 = tid >> 3, c2 = (tid & 7) * 4;
        __half h4[4];
#pragma unroll
        for (int j = 0; j < 4; j++) h4[j] = __float2half(wt[c2 + j][r2]);
        *(uint2*)(g_wh + ((size_t)(k * CO + tn * 32 + r2)) * KT + tk * 32 + c2) = *(uint2*)h4;
    }
    __syncthreads();
    __threadfence();
    if (tid == 0) atomicAdd(&g_done, 1ULL);
}

// ============================================================================
// Gram partials (symmetric): grid (GSPLIT, 3). Reads f32 x DIRECTLY with
// inline f16 conversion into swizzled smem; diag tiles also accumulate the
// per-channel column sums (cs partials). Independent of convert_all.
// ============================================================================
#define GP_PANEL 16384
#define GP_STAGE 32768
__global__ __launch_bounds__(128, 2) void gram_k(const float* __restrict__ x)
{
    extern __shared__ char smem[];
    const uint32_t sb = smem_u32(smem);
    const int tid = threadIdx.x, lane = tid & 31, w = tid >> 5;
    const int wi = w & 1, wj = w >> 1;          // 2 x 2 warp grid, 64x64
    const int s = blockIdx.x, t = blockIdx.y;
    const int ib = t >> 1, jb = (t + 1) >> 1;   // (0,0),(0,1),(1,1)
    const int diag = (ib == jb);
    const int nch = (s < 64) ? 11 : 10;         // 1024 chunks over 96 splits
    const size_t k0g = (size_t)64 * (s * 10 + (s < 64 ? s : 64));

    float csa[8];
#pragma unroll
    for (int j = 0; j < 8; j++) csa[j] = 0.f;

    // loader: LDG f32 -> cvt f16 -> STS (swizzled layout identical to before)
    auto load_c = [&](int ci) {
        uint32_t dst = sb + (uint32_t)((ci & 1) * GP_STAGE);
        size_t kk = k0g + (size_t)ci * 64;
        const int nit = diag ? 8 : 16;
#pragma unroll 4
        for (int j = 0; j < nit; j++) {
            int i = tid + 128 * j;
            int p = i >> 10, r = (i >> 4) & 63, u = i & 15;
            const float* s4 = x + (kk + r) * KT + (p ? jb : ib) * 128 + u * 8;
            float4 a = *(const float4*)s4;
            float4 bq = *(const float4*)(s4 + 4);
            float v[8] = {a.x, a.y, a.z, a.w, bq.x, bq.y, bq.z, bq.w};
            __half hh[8];
#pragma unroll
            for (int q = 0; q < 8; q++) hh[q] = __float2half(v[q]);
            if (diag) {
#pragma unroll
                for (int q = 0; q < 8; q++) csa[q] += __half2float(hh[q]);
            }
            *(uint4*)(smem + (dst - sb) + p * GP_PANEL + r * 256 +
                      (((u & 8) | ((u ^ r) & 7)) << 4)) = *(uint4*)hh;
        }
    };

    float c[4][8][4];
#pragma unroll
    for (int a = 0; a < 4; a++)
#pragma unroll
        for (int b = 0; b < 8; b++)
#pragma unroll
            for (int e = 0; e < 4; e++) c[a][b][e] = 0.f;

    const int rrL = ((lane >> 4) << 3) + (lane & 7);
    const int uoff = (lane >> 3) & 1;
    const int x7 = lane & 7;
    const uint32_t bPanel = sb + (uint32_t)((diag ? 0 : 1) * GP_PANEL);

    load_c(0);
    __syncthreads();
    for (int ci = 0; ci < nch; ci++) {
        if (ci + 1 < nch) load_c(ci + 1);
        __syncthreads();
        const uint32_t off = (uint32_t)((ci & 1) * GP_STAGE);
#pragma unroll
        for (int ks = 0; ks < 4; ks++) {
            const uint32_t rowb = (uint32_t)(ks * 4096 + rrL * 256);
            uint32_t af[4][4];
#pragma unroll
            for (int mf = 0; mf < 4; mf++) {
                int u = wi * 8 + mf * 2 + uoff;
                ldsm4t(af[mf], sb + off + rowb +
                               (uint32_t)((((u & 8) | ((u ^ x7) & 7))) << 4));
            }
            uint32_t bf[8][2];
#pragma unroll
            for (int nt2 = 0; nt2 < 4; nt2++) {
                int u = wj * 8 + nt2 * 2 + uoff;
                uint32_t r[4];
                ldsm4t(r, bPanel + off + rowb +
                          (uint32_t)((((u & 8) | ((u ^ x7) & 7))) << 4));
                bf[2 * nt2][0] = r[0]; bf[2 * nt2][1] = r[2];
                bf[2 * nt2 + 1][0] = r[1]; bf[2 * nt2 + 1][1] = r[3];
            }
#pragma unroll
            for (int mf = 0; mf < 4; mf++)
#pragma unroll
                for (int nt = 0; nt < 8; nt++) mma16816(c[mf][nt], af[mf], bf[nt]);
        }
        __syncthreads();
    }

    float* dst = g_gp + ((size_t)t * GSPLIT + s) * (128 * 128);
#pragma unroll
    for (int mf = 0; mf < 4; mf++)
#pragma unroll
        for (int nt = 0; nt < 8; nt++) {
            int i0 = wi * 64 + mf * 16 + (lane >> 2);
            int j0 = wj * 64 + nt * 8 + (lane & 3) * 2;
            *(float2*)(dst + (size_t)i0 * 128 + j0) = make_float2(c[mf][nt][0], c[mf][nt][1]);
            *(float2*)(dst + (size_t)(i0 + 8) * 128 + j0) = make_float2(c[mf][nt][2], c[mf][nt][3]);
        }

    // cs partials (diag tiles): thread tid handled ch-unit u = tid&15 for all
    // rows of this split; combine the 8 threads sharing u, write [ch][split].
    if (diag) {
        __syncthreads();
        float* red = (float*)smem;       // 128 ch x 8 partials
        const int u = tid & 15, k8 = tid >> 4;
#pragma unroll
        for (int j = 0; j < 8; j++) red[(u * 8 + j) * 8 + k8] = csa[j];
        __syncthreads();
        if (tid < 128) {
            float sum = 0.f;
#pragma unroll
            for (int k = 0; k < 8; k++) sum += red[tid * 8 + k];
            g_cspart[(size_t)(ib * 128 + tid) * GSPLIT + s] = sum;
        }
    }
}

// ============================================================================
// reduce_all: blocks [0,256): cs over 96 splits; [256,448): Gram partial
// reduce mirrored into both triangles of G. PSS-launched (sync at top).
// ============================================================================
__global__ __launch_bounds__(256) void reduce_all() {
    cudaGridDependencySynchronize();
    const int b = blockIdx.x, tid = threadIdx.x;
    if (b < 256) {
        __shared__ float sm[128];
        float v = (tid < GSPLIT) ? g_cspart[(size_t)b * GSPLIT + tid] : 0.f;
        if (tid < 128) sm[tid] = v;
        __syncthreads();
        for (int st = 64; st > 0; st >>= 1) {
            if (tid < st) sm[tid] += sm[tid + st];
            __syncthreads();
        }
        if (tid == 0) g_cs[b] = sm[0];
    } else {
        const int gb = b - 256;                 // 0..191
        const int t = gb >> 6, eb = gb & 63;
        const int ib = t >> 1, jb = (t + 1) >> 1;
        const int e = eb * 256 + tid;           // 0..16383
        float s = 0.f;
        const float* p = g_gp + (size_t)t * GSPLIT * (128 * 128) + e;
#pragma unroll 4
        for (int q = 0; q < GSPLIT; q++) s += p[(size_t)q * (128 * 128)];
        const int ii = e >> 7, jj = e & 127;
        const int gi = ib * 128 + ii, gj = jb * 128 + jj;
        g_G[gi * KT + gj] = s;
        g_G[gj * KT + gi] = s;
    }
}

// ============================================================================
// stats_part: grid CO*NOFF = 1024 blocks, one (d,k) pair each. PSS-launched:
// prefetch W (input) before the dependency sync.
// ============================================================================
__global__ __launch_bounds__(256) void stats_part(const float* __restrict__ W)
{
    const int b = blockIdx.x, j = threadIdx.x;
    const int d = b >> 3, k = b & 7;
    __shared__ float ws[KT];
    __shared__ float red[256];
    ws[j] = W[((size_t)(k * KT + j)) * CO + d];
    cudaGridDependencySynchronize();
    __syncthreads();

    float inner = 0.f;
#pragma unroll 8
    for (int i = 0; i < KT; i++)
        inner = fmaf(g_G[i * KT + j], ws[i], inner);
    float q = inner * ws[j];
    float m = g_cs[j] * ws[j];

    red[j] = q; __syncthreads();
    for (int st = 128; st > 0; st >>= 1) { if (j < st) red[j] += red[j + st]; __syncthreads(); }
    float qtot = red[0]; __syncthreads();
    red[j] = m; __syncthreads();
    for (int st = 128; st > 0; st >>= 1) { if (j < st) red[j] += red[j + st]; __syncthreads(); }
    if (j == 0) {
        g_qpart[b] = qtot;
        g_mpart[b] = red[0];
    }
}

// ============================================================================
// main GEMM: 128 thr, 2x2 warps of 64x64, fused BN+ReLU epilogue. Guards:
// g_done spin (convert outputs) at entry; PDL sync (stats) at first epilogue.
// ============================================================================
#define O_A     0
#define A_BYTES 65536                  // 128 rows x 512B (XOR swizzled)
#define O_B     A_BYTES
#define B_STAGE 16384                  // 128 n x 128B (XOR swizzled)
#define O_SC    (O_B + 3 * B_STAGE)    // 114688
#define SMEM_G  (O_SC + 1024)          // 115712 (x2 CTA = 231424 <= 233472)

__global__ __launch_bounds__(128, 2) void gemm_mma(float* __restrict__ out,
                                                   const float* __restrict__ gamma,
                                                   const float* __restrict__ beta)
{
    extern __shared__ char smem[];
    const uint32_t sb = smem_u32(smem);
    const int tid = threadIdx.x, lane = tid & 31, w = tid >> 5;
    const int wm = w & 1, wn = w >> 1;          // 2 x 2 warp grid, 64x64 tiles
    const int bx = blockIdx.x;
    float* scs = (float*)(smem + O_SC);
    float* bis = scs + CO;

    // Guard: convert_all outputs (g_xh, g_wh) ready. Monotonic counter:
    // run 1 waits for 4352; replays see a prior multiple (identical data).
    if (tid == 0) {
        unsigned long long v;
        do { v = atomicAdd(&g_done, 0ULL); } while (!(v && v % (unsigned long long)NCONVB == 0ULL));
    }
    __syncthreads();
    __threadfence();

    // A tile via cp.async (XOR swizzle): 128 rows x 32 x 16B
    {
        const __half* base = g_xh + (size_t)bx * BM * KT;
        for (int i = tid; i < 4096; i += 128) {
            int m = i >> 5, u = i & 31;
            uint32_t up = (uint32_t)((u & 24) | ((u ^ m) & 7));
            cp16(sb + O_A + m * 512 + (up << 4), base + (size_t)m * KT + u * 8);
        }
        CP_COMMIT();
    }

    auto load_b = [&](int it) {
        int ko = it >> 2, c = it & 3, st = it % 3;
        const __half* wb = g_wh + (size_t)ko * CO * KT;
        uint32_t dstb = sb + O_B + (uint32_t)(st * B_STAGE);
        for (int i = tid; i < 1024; i += 128) {
            int n = i >> 3, kb = i & 7;
            cp16(dstb + n * 128 + (uint32_t)((kb ^ (n & 7)) << 4),
                 wb + (size_t)n * KT + c * 64 + kb * 8);
        }
        CP_COMMIT();
    };
    load_b(0);
    load_b(1);

    float c[4][8][4];
#pragma unroll
    for (int mf = 0; mf < 4; mf++)
#pragma unroll
        for (int nt = 0; nt < 8; nt++)
#pragma unroll
            for (int e = 0; e < 4; e++) c[mf][nt][e] = 0.f;

    const int lrow = lane & 15, lcb = lane >> 4, xm = lane & 7;
    const uint32_t aRow = sb + O_A + (wm * 64 + lrow) * 512;
    const uint32_t bRow = sb + O_B + (wn * 64 + lrow) * 128;

    for (int it = 0; it < 32; it++) {
        if (it < 31) { CP_WAIT(1); } else { CP_WAIT(0); }
        __syncthreads();
        if (it + 2 < 32) load_b(it + 2);

        const int cch = it & 3, ko = it >> 2;
        const uint32_t stageOff = (uint32_t)((it % 3) * B_STAGE);

#pragma unroll
        for (int ks = 0; ks < 4; ks++) {
            const uint32_t xr = (uint32_t)((ks * 2 + lcb) ^ xm);
            const uint32_t au = (uint32_t)((cch * 8) << 4) + (xr << 4);
            const uint32_t bu = (xr << 4);
            uint32_t af[4][4];
#pragma unroll
            for (int mf = 0; mf < 4; mf++) ldsm4(af[mf], aRow + mf * 16 * 512 + au);
            uint32_t bfr[8][2];
#pragma unroll
            for (int p = 0; p < 4; p++) {
                uint32_t r[4];
                ldsm4(r, bRow + stageOff + p * 16 * 128 + bu);
                bfr[2 * p][0] = r[0]; bfr[2 * p][1] = r[2];
                bfr[2 * p + 1][0] = r[1]; bfr[2 * p + 1][1] = r[3];
            }
#pragma unroll
            for (int mf = 0; mf < 4; mf++)
#pragma unroll
                for (int nt = 0; nt < 8; nt++)
                    mma16816(c[mf][nt], af[mf], bfr[nt]);
        }

        if (cch == 3) {  // offset ko complete: fused BN + ReLU epilogue
            if (ko == 0) {
                cudaGridDependencySynchronize();  // stats_part complete
                {
                    float q = 0.f, m = 0.f;
#pragma unroll
                    for (int k = 0; k < NOFF; k++) {
                        q += g_qpart[tid * NOFF + k];
                        m += g_mpart[tid * NOFF + k];
                    }
                    const float invN = 1.f / (float)((size_t)NOFF * MT);
                    float mean = m * invN;
                    float var  = q * invN - mean * mean;
                    float sc   = gamma[tid] * rsqrtf(var + 1e-5f);
                    scs[tid] = sc;
                    bis[tid] = beta[tid] - mean * sc;
                }
                __syncthreads();
            }
            const size_t rbase = (size_t)ko * MT + (size_t)bx * BM + wm * 64 + (lane >> 2);
            const int colb = wn * 64 + (lane & 3) * 2;
#pragma unroll
            for (int nt = 0; nt < 8; nt++) {
                const int ch0 = colb + nt * 8;
                const float s0 = scs[ch0], s1 = scs[ch0 + 1];
                const float b0 = bis[ch0], b1 = bis[ch0 + 1];
#pragma unroll
                for (int mf = 0; mf < 4; mf++) {
                    float y0 = fmaxf(fmaf(c[mf][nt][0], s0, b0), 0.f);
                    float y1 = fmaxf(fmaf(c[mf][nt][1], s1, b1), 0.f);
                    float y2 = fmaxf(fmaf(c[mf][nt][2], s0, b0), 0.f);
                    float y3 = fmaxf(fmaf(c[mf][nt][3], s1, b1), 0.f);
                    float* p0 = out + (rbase + mf * 16) * CO + ch0;
                    *(float2*)p0 = make_float2(y0, y1);
                    *(float2*)(p0 + 8 * CO) = make_float2(y2, y3);
                }
            }
#pragma unroll
            for (int mf = 0; mf < 4; mf++)
#pragma unroll
                for (int nt = 0; nt < 8; nt++)
#pragma unroll
                    for (int e = 0; e < 4; e++) c[mf][nt][e] = 0.f;
        }
    }
}

// ============================================================================
extern "C" void kernel_launch(void* const* d_in, const int* in_sizes, int n_in,
                              void* d_out, int out_size)
{
    const float* x     = (const float*)d_in[0];   // [65536,256]
    const float* W     = (const float*)d_in[1];   // [8,256,128]
    const float* gamma = (const float*)d_in[2];
    const float* beta  = (const float*)d_in[3];
    float* out = (float*)d_out;

    cudaFuncSetAttribute(gram_k,   cudaFuncAttributeMaxDynamicSharedMemorySize, 2 * GP_STAGE);
    cudaFuncSetAttribute(gemm_mma, cudaFuncAttributeMaxDynamicSharedMemorySize, SMEM_G);

    cudaLaunchAttribute at[1];
    at[0].id = cudaLaunchAttributeProgrammaticStreamSerialization;
    at[0].val.programmaticStreamSerializationAllowed = 1;

    convert_all<<<NCONVB, 256>>>(x, W);   // triggers PDL at entry

    {   // gram overlaps convert (reads f32 x directly)
        cudaLaunchConfig_t cfg = {};
        cfg.gridDim = dim3(GSPLIT, GTILES);
        cfg.blockDim = dim3(128);
        cfg.dynamicSmemBytes = 2 * GP_STAGE;
        cfg.stream = 0;
        cfg.attrs = at; cfg.numAttrs = 1;
        cudaLaunchKernelEx(&cfg, gram_k, x);
    }
    {   // reduce (syncs on gram inside)
        cudaLaunchConfig_t cfg = {};
        cfg.gridDim = dim3(448);
        cfg.blockDim = dim3(256);
        cfg.stream = 0;
        cfg.attrs = at; cfg.numAttrs = 1;
        cudaLaunchKernelEx(&cfg, reduce_all);
    }
    {   // stats partials (prefetch W, then sync on reduce)
        cudaLaunchConfig_t cfg = {};
        cfg.gridDim = dim3(CO * NOFF);
        cfg.blockDim = dim3(256);
        cfg.stream = 0;
        cfg.attrs = at; cfg.numAttrs = 1;
        cudaLaunchKernelEx(&cfg, stats_part, W);
    }
    {   // gemm (spin-guard on convert; PDL sync on stats at first epilogue)
        cudaLaunchConfig_t cfg = {};
        cfg.gridDim = dim3(MTILES);
        cfg.blockDim = dim3(128);
        cfg.dynamicSmemBytes = SMEM_G;
        cfg.stream = 0;
        cfg.attrs = at; cfg.numAttrs = 1;
        cudaLaunchKernelEx(&cfg, gemm_mma, out, gamma, beta);
    }
}

// round 15
// speedup vs baseline: 1.1181x; 1.1181x over previous
#include <cuda_runtime.h>
#include <cuda_fp16.h>
#include <cstdint>

// ============================================================================
// Upsample: out = stack_k(x @ W[k]) [8*65536,128] -> BN(train stats) -> ReLU
// fp16 mma.sync (f32 accum) at the legacy-HMMA ceiling. R15 = R13 (revert the
// R14 convert||gram experiment) + PSS launch & early-sync on reduce_all and
// stats_part (W prefetch hidden under the dependency wait).
// ============================================================================

#define MT      65536
#define KT      256
#define CO      128
#define NOFF    8
#define BM      128
#define MTILES  512
#define GSPLIT  96            // k-splits for Gram
#define GTILES  3             // symmetric 128x128 blocks: (0,0),(0,1),(1,1)
#define MBLK    (MT / 64)     // 1024 convert blocks along M

// ---- device scratch ----
__device__ __align__(16) __half g_xh[(size_t)MT * KT];        // row-major
__device__ __align__(16) __half g_wh[NOFF * CO * KT];         // [k][n][kk]
__device__ float g_gp[(size_t)GTILES * GSPLIT * 128 * 128];   // Gram partials
__device__ float g_G [KT * KT];
__device__ float g_cspart[KT * MBLK];                         // [ch][mblk]
__device__ float g_cs[KT];
__device__ float g_qpart[CO * NOFF];                          // [d][k]
__device__ float g_mpart[CO * NOFF];                          // [d][k]

// ---- PTX helpers ----
__device__ __forceinline__ uint32_t smem_u32(const void* p) {
    uint32_t a;
    asm("{ .reg .u64 t; cvta.to.shared.u64 t, %1; cvt.u32.u64 %0, t; }" : "=r"(a) : "l"(p));
    return a;
}
__device__ __forceinline__ void cp16(uint32_t dst, const void* src) {
    asm volatile("cp.async.cg.shared.global [%0], [%1], 16;" :: "r"(dst), "l"(src) : "memory");
}
#define CP_COMMIT() asm volatile("cp.async.commit_group;" ::: "memory")
#define CP_WAIT(n)  asm volatile("cp.async.wait_group %0;" :: "n"(n) : "memory")

__device__ __forceinline__ void ldsm4(uint32_t r[4], uint32_t a) {
    asm volatile("ldmatrix.sync.aligned.m8n8.x4.shared.b16 {%0,%1,%2,%3}, [%4];"
                 : "=r"(r[0]), "=r"(r[1]), "=r"(r[2]), "=r"(r[3]) : "r"(a));
}
__device__ __forceinline__ void ldsm4t(uint32_t r[4], uint32_t a) {
    asm volatile("ldmatrix.sync.aligned.m8n8.x4.trans.shared.b16 {%0,%1,%2,%3}, [%4];"
                 : "=r"(r[0]), "=r"(r[1]), "=r"(r[2]), "=r"(r[3]) : "r"(a));
}
__device__ __forceinline__ void mma16816(float d[4], const uint32_t a[4], const uint32_t b[2]) {
    asm volatile(
        "mma.sync.aligned.m16n8k16.row.col.f32.f16.f16.f32 "
        "{%0,%1,%2,%3}, {%4,%5,%6,%7}, {%8,%9}, {%0,%1,%2,%3};"
        : "+f"(d[0]), "+f"(d[1]), "+f"(d[2]), "+f"(d[3])
        : "r"(a[0]), "r"(a[1]), "r"(a[2]), "r"(a[3]), "r"(b[0]), "r"(b[1]));
}

// ============================================================================
// convert_all: blocks [0,4096): x -> fp16 + cs partials (streaming)
//              blocks [4096,4352): W 32x32 tile transpose-convert -> g_wh
// ============================================================================
__global__ __launch_bounds__(256) void convert_all(const float* __restrict__ x,
                                                   const float* __restrict__ W) {
    const int b = blockIdx.x, tid = threadIdx.x;
    if (b < 4096) {
        __shared__ float red[8][8][8];   // [warp][ch-octet][j]
        const int lane = tid & 31, w = tid >> 5;
        const int bx = b >> 2, by = b & 3;
        const int r0 = bx * 64, c0 = by * 64;
        const int cl = (tid & 7) * 8;
        float s[8];
#pragma unroll
        for (int j = 0; j < 8; j++) s[j] = 0.f;
#pragma unroll
        for (int h = 0; h < 2; h++) {
            int rl = h * 32 + (tid >> 3);
            const float* src = x + (size_t)(r0 + rl) * KT + c0 + cl;
            float4 f0 = *(const float4*)src;
            float4 f1 = *(const float4*)(src + 4);
            float v[8] = {f0.x, f0.y, f0.z, f0.w, f1.x, f1.y, f1.z, f1.w};
            __half hh[8];
#pragma unroll
            for (int j = 0; j < 8; j++) {
                hh[j] = __float2half(v[j]);
                s[j] += __half2float(hh[j]);
            }
            *(uint4*)(g_xh + (size_t)(r0 + rl) * KT + c0 + cl) = *(uint4*)hh;
        }
#pragma unroll
        for (int j = 0; j < 8; j++) {
            s[j] += __shfl_down_sync(0xffffffffu, s[j], 16);
            s[j] += __shfl_down_sync(0xffffffffu, s[j], 8);
        }
        if (lane < 8) {
#pragma unroll
            for (int j = 0; j < 8; j++) red[w][lane][j] = s[j];
        }
        __syncthreads();
        if (tid < 64) {
            float t = 0.f;
#pragma unroll
            for (int ww = 0; ww < 8; ww++) t += red[ww][tid >> 3][tid & 7];
            g_cspart[(size_t)(c0 + tid) * MBLK + bx] = t;
        }
    } else {
        // W transpose-convert: W[k][kk][n] (f32) -> g_wh[k][n][kk] (f16)
        __shared__ float wt[32][33];
        const int t = b - 4096;          // 0..255
        const int k = t >> 5, tile = t & 31;
        const int tk = tile >> 2, tn = tile & 3;
#pragma unroll
        for (int p = 0; p < 4; p++) {
            int row = p * 8 + (tid >> 5), col = tid & 31;
            wt[row][col] = W[((size_t)(k * KT + tk * 32 + row)) * CO + tn * 32 + col];
        }
        __syncthreads();
        const int r2 = tid >> 3, c2 = (tid & 7) * 4;
        __half h4[4];
#pragma unroll
        for (int j = 0; j < 4; j++) h4[j] = __float2half(wt[c2 + j][r2]);
        *(uint2*)(g_wh + ((size_t)(k * CO + tn * 32 + r2)) * KT + tk * 32 + c2) = *(uint2*)h4;
    }
}

// ============================================================================
// Gram partials (symmetric): grid (GSPLIT, 3). 128 thr, warps 2x2 of 64x64
// over a 128x128 ch tile; ldmatrix.x4.trans directly from row-major g_xh.
// ============================================================================
#define GP_PANEL 16384
#define GP_STAGE 32768
__global__ __launch_bounds__(128, 2) void gram_k()
{
    extern __shared__ char smem[];
    const uint32_t sb = smem_u32(smem);
    const int tid = threadIdx.x, lane = tid & 31, w = tid >> 5;
    const int wi = w & 1, wj = w >> 1;          // 2 x 2 warp grid, 64x64
    const int s = blockIdx.x, t = blockIdx.y;
    const int ib = t >> 1, jb = (t + 1) >> 1;   // (0,0),(0,1),(1,1)
    const int diag = (ib == jb);
    const int nch = (s < 64) ? 11 : 10;         // 1024 chunks over 96 splits
    const size_t k0g = (size_t)64 * (s * 10 + (s < 64 ? s : 64));

    auto load_c = [&](int ci) {
        uint32_t dst = sb + (uint32_t)((ci & 1) * GP_STAGE);
        size_t kk = k0g + (size_t)ci * 64;
        const int tot = diag ? 1024 : 2048;
        for (int i = tid; i < tot; i += 128) {
            int p = i >> 10, r = (i >> 4) & 63, u = i & 15;
            int chg = (p ? jb : ib) * 128 + u * 8;
            cp16(dst + (uint32_t)(p * GP_PANEL + r * 256 +
                                  (((u & 8) | ((u ^ r) & 7)) << 4)),
                 g_xh + (kk + r) * KT + chg);
        }
        CP_COMMIT();
    };
    load_c(0);

    float c[4][8][4];
#pragma unroll
    for (int a = 0; a < 4; a++)
#pragma unroll
        for (int b = 0; b < 8; b++)
#pragma unroll
            for (int e = 0; e < 4; e++) c[a][b][e] = 0.f;

    const int rrL = ((lane >> 4) << 3) + (lane & 7);
    const int uoff = (lane >> 3) & 1;
    const int x7 = lane & 7;
    const uint32_t bPanel = sb + (uint32_t)((diag ? 0 : 1) * GP_PANEL);

    for (int ci = 0; ci < nch; ci++) {
        CP_WAIT(0);
        __syncthreads();
        if (ci + 1 < nch) load_c(ci + 1);
        const uint32_t off = (uint32_t)((ci & 1) * GP_STAGE);
#pragma unroll
        for (int ks = 0; ks < 4; ks++) {
            const uint32_t rowb = (uint32_t)(ks * 4096 + rrL * 256);
            uint32_t af[4][4];
#pragma unroll
            for (int mf = 0; mf < 4; mf++) {
                int u = wi * 8 + mf * 2 + uoff;
                ldsm4t(af[mf], sb + off + rowb +
                               (uint32_t)((((u & 8) | ((u ^ x7) & 7))) << 4));
            }
            uint32_t bf[8][2];
#pragma unroll
            for (int nt2 = 0; nt2 < 4; nt2++) {
                int u = wj * 8 + nt2 * 2 + uoff;
                uint32_t r[4];
                ldsm4t(r, bPanel + off + rowb +
                          (uint32_t)((((u & 8) | ((u ^ x7) & 7))) << 4));
                bf[2 * nt2][0] = r[0]; bf[2 * nt2][1] = r[2];
                bf[2 * nt2 + 1][0] = r[1]; bf[2 * nt2 + 1][1] = r[3];
            }
#pragma unroll
            for (int mf = 0; mf < 4; mf++)
#pragma unroll
                for (int nt = 0; nt < 8; nt++) mma16816(c[mf][nt], af[mf], bf[nt]);
        }
    }

    float* dst = g_gp + ((size_t)t * GSPLIT + s) * (128 * 128);
#pragma unroll
    for (int mf = 0; mf < 4; mf++)
#pragma unroll
        for (int nt = 0; nt < 8; nt++) {
            int i0 = wi * 64 + mf * 16 + (lane >> 2);
            int j0 = wj * 64 + nt * 8 + (lane & 3) * 2;
            *(float2*)(dst + (size_t)i0 * 128 + j0) = make_float2(c[mf][nt][0], c[mf][nt][1]);
            *(float2*)(dst + (size_t)(i0 + 8) * 128 + j0) = make_float2(c[mf][nt][2], c[mf][nt][3]);
        }
}

// ============================================================================
// reduce_all (PSS): blocks [0,256): colsum reduce; [256,448): Gram partial
// reduce mirrored into both triangles of G. Sync at top (launch-gap hiding).
// ============================================================================
__global__ __launch_bounds__(256) void reduce_all() {
    cudaGridDependencySynchronize();
    const int b = blockIdx.x, tid = threadIdx.x;
    if (b < 256) {
        const float* p = g_cspart + (size_t)b * MBLK + tid * 4;
        float s = p[0] + p[1] + p[2] + p[3];
        __shared__ float sm[256];
        sm[tid] = s; __syncthreads();
        for (int st = 128; st > 0; st >>= 1) {
            if (tid < st) sm[tid] += sm[tid + st];
            __syncthreads();
        }
        if (tid == 0) g_cs[b] = sm[0];
    } else {
        const int gb = b - 256;                 // 0..191
        const int t = gb >> 6, eb = gb & 63;
        const int ib = t >> 1, jb = (t + 1) >> 1;
        const int e = eb * 256 + tid;           // 0..16383
        float s = 0.f;
        const float* p = g_gp + (size_t)t * GSPLIT * (128 * 128) + e;
#pragma unroll 4
        for (int q = 0; q < GSPLIT; q++) s += p[(size_t)q * (128 * 128)];
        const int ii = e >> 7, jj = e & 127;
        const int gi = ib * 128 + ii, gj = jb * 128 + jj;
        g_G[gi * KT + gj] = s;
        g_G[gj * KT + gi] = s;
    }
}

// ============================================================================
// stats_part (PSS): grid CO*NOFF = 1024 blocks, one (d,k) pair each. W slice
// prefetched into smem BEFORE the dependency sync (hidden under the wait).
// ============================================================================
__global__ __launch_bounds__(256) void stats_part(const float* __restrict__ W)
{
    const int b = blockIdx.x, j = threadIdx.x;
    const int d = b >> 3, k = b & 7;
    __shared__ float ws[KT];
    __shared__ float red[256];
    ws[j] = W[((size_t)(k * KT + j)) * CO + d];
    cudaGridDependencySynchronize();
    __syncthreads();

    float inner = 0.f;
#pragma unroll 8
    for (int i = 0; i < KT; i++)
        inner = fmaf(g_G[i * KT + j], ws[i], inner);
    float q = inner * ws[j];
    float m = g_cs[j] * ws[j];

    red[j] = q; __syncthreads();
    for (int st = 128; st > 0; st >>= 1) { if (j < st) red[j] += red[j + st]; __syncthreads(); }
    float qtot = red[0]; __syncthreads();
    red[j] = m; __syncthreads();
    for (int st = 128; st > 0; st >>= 1) { if (j < st) red[j] += red[j + st]; __syncthreads(); }
    if (j == 0) {
        g_qpart[b] = qtot;
        g_mpart[b] = red[0];
    }
}

// ============================================================================
// main GEMM: 128 thr, 2x2 warps of 64x64, fused BN+ReLU epilogue. PDL: the
// prologue/mainloop overlap stats_part; at ko==0 the CTA finalizes BN
// scale/bias from the (d,k) partials into smem.
// ============================================================================
#define O_A     0
#define A_BYTES 65536                  // 128 rows x 512B (XOR swizzled)
#define O_B     A_BYTES
#define B_STAGE 16384                  // 128 n x 128B (XOR swizzled)
#define O_SC    (O_B + 3 * B_STAGE)    // 114688
#define SMEM_G  (O_SC + 1024)          // 115712 (x2 CTA = 231424 <= 233472)

__global__ __launch_bounds__(128, 2) void gemm_mma(float* __restrict__ out,
                                                   const float* __restrict__ gamma,
                                                   const float* __restrict__ beta)
{
    extern __shared__ char smem[];
    const uint32_t sb = smem_u32(smem);
    const int tid = threadIdx.x, lane = tid & 31, w = tid >> 5;
    const int wm = w & 1, wn = w >> 1;          // 2 x 2 warp grid, 64x64 tiles
    const int bx = blockIdx.x;
    float* scs = (float*)(smem + O_SC);
    float* bis = scs + CO;

    // A tile via cp.async (XOR swizzle): 128 rows x 32 x 16B
    {
        const __half* base = g_xh + (size_t)bx * BM * KT;
        for (int i = tid; i < 4096; i += 128) {
            int m = i >> 5, u = i & 31;
            uint32_t up = (uint32_t)((u & 24) | ((u ^ m) & 7));
            cp16(sb + O_A + m * 512 + (up << 4), base + (size_t)m * KT + u * 8);
        }
        CP_COMMIT();
    }

    auto load_b = [&](int it) {
        int ko = it >> 2, c = it & 3, st = it % 3;
        const __half* wb = g_wh + (size_t)ko * CO * KT;
        uint32_t dstb = sb + O_B + (uint32_t)(st * B_STAGE);
        for (int i = tid; i < 1024; i += 128) {
            int n = i >> 3, kb = i & 7;
            cp16(dstb + n * 128 + (uint32_t)((kb ^ (n & 7)) << 4),
                 wb + (size_t)n * KT + c * 64 + kb * 8);
        }
        CP_COMMIT();
    };
    load_b(0);
    load_b(1);

    float c[4][8][4];
#pragma unroll
    for (int mf = 0; mf < 4; mf++)
#pragma unroll
        for (int nt = 0; nt < 8; nt++)
#pragma unroll
            for (int e = 0; e < 4; e++) c[mf][nt][e] = 0.f;

    const int lrow = lane & 15, lcb = lane >> 4, xm = lane & 7;
    const uint32_t aRow = sb + O_A + (wm * 64 + lrow) * 512;
    const uint32_t bRow = sb + O_B + (wn * 64 + lrow) * 128;

    for (int it = 0; it < 32; it++) {
        if (it < 31) { CP_WAIT(1); } else { CP_WAIT(0); }
        __syncthreads();
        if (it + 2 < 32) load_b(it + 2);

        const int cch = it & 3, ko = it >> 2;
        const uint32_t stageOff = (uint32_t)((it % 3) * B_STAGE);

#pragma unroll
        for (int ks = 0; ks < 4; ks++) {
            const uint32_t xr = (uint32_t)((ks * 2 + lcb) ^ xm);
            const uint32_t au = (uint32_t)((cch * 8) << 4) + (xr << 4);
            const uint32_t bu = (xr << 4);
            uint32_t af[4][4];
#pragma unroll
            for (int mf = 0; mf < 4; mf++) ldsm4(af[mf], aRow + mf * 16 * 512 + au);
            uint32_t bfr[8][2];
#pragma unroll
            for (int p = 0; p < 4; p++) {
                uint32_t r[4];
                ldsm4(r, bRow + stageOff + p * 16 * 128 + bu);
                bfr[2 * p][0] = r[0]; bfr[2 * p][1] = r[2];
                bfr[2 * p + 1][0] = r[1]; bfr[2 * p + 1][1] = r[3];
            }
#pragma unroll
            for (int mf = 0; mf < 4; mf++)
#pragma unroll
                for (int nt = 0; nt < 8; nt++)
                    mma16816(c[mf][nt], af[mf], bfr[nt]);
        }

        if (cch == 3) {  // offset ko complete: fused BN + ReLU epilogue
            if (ko == 0) {
                cudaGridDependencySynchronize();  // stats_part complete
                {
                    float q = 0.f, m = 0.f;
#pragma unroll
                    for (int k = 0; k < NOFF; k++) {
                        q += g_qpart[tid * NOFF + k];
                        m += g_mpart[tid * NOFF + k];
                    }
                    const float invN = 1.f / (float)((size_t)NOFF * MT);
                    float mean = m * invN;
                    float var  = q * invN - mean * mean;
                    float sc   = gamma[tid] * rsqrtf(var + 1e-5f);
                    scs[tid] = sc;
                    bis[tid] = beta[tid] - mean * sc;
                }
                __syncthreads();
            }
            const size_t rbase = (size_t)ko * MT + (size_t)bx * BM + wm * 64 + (lane >> 2);
            const int colb = wn * 64 + (lane & 3) * 2;
#pragma unroll
            for (int nt = 0; nt < 8; nt++) {
                const int ch0 = colb + nt * 8;
                const float s0 = scs[ch0], s1 = scs[ch0 + 1];
                const float b0 = bis[ch0], b1 = bis[ch0 + 1];
#pragma unroll
                for (int mf = 0; mf < 4; mf++) {
                    float y0 = fmaxf(fmaf(c[mf][nt][0], s0, b0), 0.f);
                    float y1 = fmaxf(fmaf(c[mf][nt][1], s1, b1), 0.f);
                    float y2 = fmaxf(fmaf(c[mf][nt][2], s0, b0), 0.f);
                    float y3 = fmaxf(fmaf(c[mf][nt][3], s1, b1), 0.f);
                    float* p0 = out + (rbase + mf * 16) * CO + ch0;
                    *(float2*)p0 = make_float2(y0, y1);
                    *(float2*)(p0 + 8 * CO) = make_float2(y2, y3);
                }
            }
#pragma unroll
            for (int mf = 0; mf < 4; mf++)
#pragma unroll
                for (int nt = 0; nt < 8; nt++)
#pragma unroll
                    for (int e = 0; e < 4; e++) c[mf][nt][e] = 0.f;
        }
    }
}

// ============================================================================
extern "C" void kernel_launch(void* const* d_in, const int* in_sizes, int n_in,
                              void* d_out, int out_size)
{
    const float* x     = (const float*)d_in[0];   // [65536,256]
    const float* W     = (const float*)d_in[1];   // [8,256,128]
    const float* gamma = (const float*)d_in[2];
    const float* beta  = (const float*)d_in[3];
    float* out = (float*)d_out;

    cudaFuncSetAttribute(gram_k,   cudaFuncAttributeMaxDynamicSharedMemorySize, 2 * GP_STAGE);
    cudaFuncSetAttribute(gemm_mma, cudaFuncAttributeMaxDynamicSharedMemorySize, SMEM_G);

    cudaLaunchAttribute at[1];
    at[0].id = cudaLaunchAttributeProgrammaticStreamSerialization;
    at[0].val.programmaticStreamSerializationAllowed = 1;

    convert_all<<<4096 + 256, 256>>>(x, W);
    dim3 ggrid(GSPLIT, GTILES);
    gram_k<<<ggrid, 128, 2 * GP_STAGE>>>();

    {   // reduce (PSS; syncs at top)
        cudaLaunchConfig_t cfg = {};
        cfg.gridDim = dim3(448);
        cfg.blockDim = dim3(256);
        cfg.stream = 0;
        cfg.attrs = at; cfg.numAttrs = 1;
        cudaLaunchKernelEx(&cfg, reduce_all);
    }
    {   // stats partials (PSS; prefetch W before sync)
        cudaLaunchConfig_t cfg = {};
        cfg.gridDim = dim3(CO * NOFF);
        cfg.blockDim = dim3(256);
        cfg.stream = 0;
        cfg.attrs = at; cfg.numAttrs = 1;
        cudaLaunchKernelEx(&cfg, stats_part, W);
    }
    {   // gemm (PDL; prologue overlaps stats_part)
        cudaLaunchConfig_t cfg = {};
        cfg.gridDim = dim3(MTILES);
        cfg.blockDim = dim3(128);
        cfg.dynamicSmemBytes = SMEM_G;
        cfg.stream = 0;
        cfg.attrs = at; cfg.numAttrs = 1;
        cudaLaunchKernelEx(&cfg, gemm_mma, out, gamma, beta);
    }
}

// round 16
// speedup vs baseline: 1.2174x; 1.0888x over previous
#include <cuda_runtime.h>
#include <cuda_fp16.h>
#include <cstdint>

// ============================================================================
// Upsample: out = stack_k(x @ W[k]) [8*65536,128] -> BN(train stats) -> ReLU
// fp16 mma.sync (f32 accum) at the legacy-HMMA ceiling. R16: persistent gemm
// (296 CTAs, strided (tile,offset) unit list) to kill 2-wave quantization;
// reduce/stats back to plain launches (R15's PSS spin cost reverted).
// ============================================================================

#define MT      65536
#define KT      256
#define CO      128
#define NOFF    8
#define BM      128
#define MTILES  512
#define NUNITS  4096          // 512 tiles x 8 offsets
#define NCTA    296           // 148 SMs x 2 CTAs
#define GSPLIT  96            // k-splits for Gram
#define GTILES  3             // symmetric 128x128 blocks: (0,0),(0,1),(1,1)
#define MBLK    (MT / 64)     // 1024 convert blocks along M

// ---- device scratch ----
__device__ __align__(16) __half g_xh[(size_t)MT * KT];        // row-major
__device__ __align__(16) __half g_wh[NOFF * CO * KT];         // [k][n][kk]
__device__ float g_gp[(size_t)GTILES * GSPLIT * 128 * 128];   // Gram partials
__device__ float g_G [KT * KT];
__device__ float g_cspart[KT * MBLK];                         // [ch][mblk]
__device__ float g_cs[KT];
__device__ float g_qpart[CO * NOFF];                          // [d][k]
__device__ float g_mpart[CO * NOFF];                          // [d][k]

// ---- PTX helpers ----
__device__ __forceinline__ uint32_t smem_u32(const void* p) {
    uint32_t a;
    asm("{ .reg .u64 t; cvta.to.shared.u64 t, %1; cvt.u32.u64 %0, t; }" : "=r"(a) : "l"(p));
    return a;
}
__device__ __forceinline__ void cp16(uint32_t dst, const void* src) {
    asm volatile("cp.async.cg.shared.global [%0], [%1], 16;" :: "r"(dst), "l"(src) : "memory");
}
#define CP_COMMIT() asm volatile("cp.async.commit_group;" ::: "memory")
#define CP_WAIT(n)  asm volatile("cp.async.wait_group %0;" :: "n"(n) : "memory")

__device__ __forceinline__ void ldsm4(uint32_t r[4], uint32_t a) {
    asm volatile("ldmatrix.sync.aligned.m8n8.x4.shared.b16 {%0,%1,%2,%3}, [%4];"
                 : "=r"(r[0]), "=r"(r[1]), "=r"(r[2]), "=r"(r[3]) : "r"(a));
}
__device__ __forceinline__ void ldsm4t(uint32_t r[4], uint32_t a) {
    asm volatile("ldmatrix.sync.aligned.m8n8.x4.trans.shared.b16 {%0,%1,%2,%3}, [%4];"
                 : "=r"(r[0]), "=r"(r[1]), "=r"(r[2]), "=r"(r[3]) : "r"(a));
}
__device__ __forceinline__ void mma16816(float d[4], const uint32_t a[4], const uint32_t b[2]) {
    asm volatile(
        "mma.sync.aligned.m16n8k16.row.col.f32.f16.f16.f32 "
        "{%0,%1,%2,%3}, {%4,%5,%6,%7}, {%8,%9}, {%0,%1,%2,%3};"
        : "+f"(d[0]), "+f"(d[1]), "+f"(d[2]), "+f"(d[3])
        : "r"(a[0]), "r"(a[1]), "r"(a[2]), "r"(a[3]), "r"(b[0]), "r"(b[1]));
}

// ============================================================================
// convert_all: blocks [0,4096): x -> fp16 + cs partials (streaming)
//              blocks [4096,4352): W 32x32 tile transpose-convert -> g_wh
// ============================================================================
__global__ __launch_bounds__(256) void convert_all(const float* __restrict__ x,
                                                   const float* __restrict__ W) {
    const int b = blockIdx.x, tid = threadIdx.x;
    if (b < 4096) {
        __shared__ float red[8][8][8];   // [warp][ch-octet][j]
        const int lane = tid & 31, w = tid >> 5;
        const int bx = b >> 2, by = b & 3;
        const int r0 = bx * 64, c0 = by * 64;
        const int cl = (tid & 7) * 8;
        float s[8];
#pragma unroll
        for (int j = 0; j < 8; j++) s[j] = 0.f;
#pragma unroll
        for (int h = 0; h < 2; h++) {
            int rl = h * 32 + (tid >> 3);
            const float* src = x + (size_t)(r0 + rl) * KT + c0 + cl;
            float4 f0 = *(const float4*)src;
            float4 f1 = *(const float4*)(src + 4);
            float v[8] = {f0.x, f0.y, f0.z, f0.w, f1.x, f1.y, f1.z, f1.w};
            __half hh[8];
#pragma unroll
            for (int j = 0; j < 8; j++) {
                hh[j] = __float2half(v[j]);
                s[j] += __half2float(hh[j]);
            }
            *(uint4*)(g_xh + (size_t)(r0 + rl) * KT + c0 + cl) = *(uint4*)hh;
        }
#pragma unroll
        for (int j = 0; j < 8; j++) {
            s[j] += __shfl_down_sync(0xffffffffu, s[j], 16);
            s[j] += __shfl_down_sync(0xffffffffu, s[j], 8);
        }
        if (lane < 8) {
#pragma unroll
            for (int j = 0; j < 8; j++) red[w][lane][j] = s[j];
        }
        __syncthreads();
        if (tid < 64) {
            float t = 0.f;
#pragma unroll
            for (int ww = 0; ww < 8; ww++) t += red[ww][tid >> 3][tid & 7];
            g_cspart[(size_t)(c0 + tid) * MBLK + bx] = t;
        }
    } else {
        // W transpose-convert: W[k][kk][n] (f32) -> g_wh[k][n][kk] (f16)
        __shared__ float wt[32][33];
        const int t = b - 4096;          // 0..255
        const int k = t >> 5, tile = t & 31;
        const int tk = tile >> 2, tn = tile & 3;
#pragma unroll
        for (int p = 0; p < 4; p++) {
            int row = p * 8 + (tid >> 5), col = tid & 31;
            wt[row][col] = W[((size_t)(k * KT + tk * 32 + row)) * CO + tn * 32 + col];
        }
        __syncthreads();
        const int r2 = tid >> 3, c2 = (tid & 7) * 4;
        __half h4[4];
#pragma unroll
        for (int j = 0; j < 4; j++) h4[j] = __float2half(wt[c2 + j][r2]);
        *(uint2*)(g_wh + ((size_t)(k * CO + tn * 32 + r2)) * KT + tk * 32 + c2) = *(uint2*)h4;
    }
}

// ============================================================================
// Gram partials (symmetric): grid (GSPLIT, 3). 128 thr, warps 2x2 of 64x64
// over a 128x128 ch tile; ldmatrix.x4.trans directly from row-major g_xh.
// ============================================================================
#define GP_PANEL 16384
#define GP_STAGE 32768
__global__ __launch_bounds__(128, 2) void gram_k()
{
    extern __shared__ char smem[];
    const uint32_t sb = smem_u32(smem);
    const int tid = threadIdx.x, lane = tid & 31, w = tid >> 5;
    const int wi = w & 1, wj = w >> 1;          // 2 x 2 warp grid, 64x64
    const int s = blockIdx.x, t = blockIdx.y;
    const int ib = t >> 1, jb = (t + 1) >> 1;   // (0,0),(0,1),(1,1)
    const int diag = (ib == jb);
    const int nch = (s < 64) ? 11 : 10;         // 1024 chunks over 96 splits
    const size_t k0g = (size_t)64 * (s * 10 + (s < 64 ? s : 64));

    auto load_c = [&](int ci) {
        uint32_t dst = sb + (uint32_t)((ci & 1) * GP_STAGE);
        size_t kk = k0g + (size_t)ci * 64;
        const int tot = diag ? 1024 : 2048;
        for (int i = tid; i < tot; i += 128) {
            int p = i >> 10, r = (i >> 4) & 63, u = i & 15;
            int chg = (p ? jb : ib) * 128 + u * 8;
            cp16(dst + (uint32_t)(p * GP_PANEL + r * 256 +
                                  (((u & 8) | ((u ^ r) & 7)) << 4)),
                 g_xh + (kk + r) * KT + chg);
        }
        CP_COMMIT();
    };
    load_c(0);

    float c[4][8][4];
#pragma unroll
    for (int a = 0; a < 4; a++)
#pragma unroll
        for (int b = 0; b < 8; b++)
#pragma unroll
            for (int e = 0; e < 4; e++) c[a][b][e] = 0.f;

    const int rrL = ((lane >> 4) << 3) + (lane & 7);
    const int uoff = (lane >> 3) & 1;
    const int x7 = lane & 7;
    const uint32_t bPanel = sb + (uint32_t)((diag ? 0 : 1) * GP_PANEL);

    for (int ci = 0; ci < nch; ci++) {
        CP_WAIT(0);
        __syncthreads();
        if (ci + 1 < nch) load_c(ci + 1);
        const uint32_t off = (uint32_t)((ci & 1) * GP_STAGE);
#pragma unroll
        for (int ks = 0; ks < 4; ks++) {
            const uint32_t rowb = (uint32_t)(ks * 4096 + rrL * 256);
            uint32_t af[4][4];
#pragma unroll
            for (int mf = 0; mf < 4; mf++) {
                int u = wi * 8 + mf * 2 + uoff;
                ldsm4t(af[mf], sb + off + rowb +
                               (uint32_t)((((u & 8) | ((u ^ x7) & 7))) << 4));
            }
            uint32_t bf[8][2];
#pragma unroll
            for (int nt2 = 0; nt2 < 4; nt2++) {
                int u = wj * 8 + nt2 * 2 + uoff;
                uint32_t r[4];
                ldsm4t(r, bPanel + off + rowb +
                          (uint32_t)((((u & 8) | ((u ^ x7) & 7))) << 4));
                bf[2 * nt2][0] = r[0]; bf[2 * nt2][1] = r[2];
                bf[2 * nt2 + 1][0] = r[1]; bf[2 * nt2 + 1][1] = r[3];
            }
#pragma unroll
            for (int mf = 0; mf < 4; mf++)
#pragma unroll
                for (int nt = 0; nt < 8; nt++) mma16816(c[mf][nt], af[mf], bf[nt]);
        }
    }

    float* dst = g_gp + ((size_t)t * GSPLIT + s) * (128 * 128);
#pragma unroll
    for (int mf = 0; mf < 4; mf++)
#pragma unroll
        for (int nt = 0; nt < 8; nt++) {
            int i0 = wi * 64 + mf * 16 + (lane >> 2);
            int j0 = wj * 64 + nt * 8 + (lane & 3) * 2;
            *(float2*)(dst + (size_t)i0 * 128 + j0) = make_float2(c[mf][nt][0], c[mf][nt][1]);
            *(float2*)(dst + (size_t)(i0 + 8) * 128 + j0) = make_float2(c[mf][nt][2], c[mf][nt][3]);
        }
}

// ============================================================================
// reduce_all: blocks [0,256): colsum reduce; [256,448): Gram partial reduce
// (mirrored into both triangles of G)
// ============================================================================
__global__ __launch_bounds__(256) void reduce_all() {
    const int b = blockIdx.x, tid = threadIdx.x;
    if (b < 256) {
        const float* p = g_cspart + (size_t)b * MBLK + tid * 4;
        float s = p[0] + p[1] + p[2] + p[3];
        __shared__ float sm[256];
        sm[tid] = s; __syncthreads();
        for (int st = 128; st > 0; st >>= 1) {
            if (tid < st) sm[tid] += sm[tid + st];
            __syncthreads();
        }
        if (tid == 0) g_cs[b] = sm[0];
    } else {
        const int gb = b - 256;                 // 0..191
        const int t = gb >> 6, eb = gb & 63;
        const int ib = t >> 1, jb = (t + 1) >> 1;
        const int e = eb * 256 + tid;           // 0..16383
        float s = 0.f;
        const float* p = g_gp + (size_t)t * GSPLIT * (128 * 128) + e;
#pragma unroll 4
        for (int q = 0; q < GSPLIT; q++) s += p[(size_t)q * (128 * 128)];
        const int ii = e >> 7, jj = e & 127;
        const int gi = ib * 128 + ii, gj = jb * 128 + jj;
        g_G[gi * KT + gj] = s;
        g_G[gj * KT + gi] = s;
    }
}

// ============================================================================
// stats_part: grid CO*NOFF = 1024 blocks, one (d,k) pair each.
// ============================================================================
__global__ __launch_bounds__(256) void stats_part(const float* __restrict__ W)
{
    const int b = blockIdx.x, j = threadIdx.x;
    const int d = b >> 3, k = b & 7;
    __shared__ float ws[KT];
    __shared__ float red[256];
    ws[j] = W[((size_t)(k * KT + j)) * CO + d];
    __syncthreads();

    float inner = 0.f;
#pragma unroll 8
    for (int i = 0; i < KT; i++)
        inner = fmaf(g_G[i * KT + j], ws[i], inner);
    float q = inner * ws[j];
    float m = g_cs[j] * ws[j];

    red[j] = q; __syncthreads();
    for (int st = 128; st > 0; st >>= 1) { if (j < st) red[j] += red[j + st]; __syncthreads(); }
    float qtot = red[0]; __syncthreads();
    red[j] = m; __syncthreads();
    for (int st = 128; st > 0; st >>= 1) { if (j < st) red[j] += red[j + st]; __syncthreads(); }
    if (j == 0) {
        g_qpart[b] = qtot;
        g_mpart[b] = red[0];
    }
}

// ============================================================================
// Persistent GEMM: 296 CTAs, 128 thr, 2x2 warps of 64x64. Each CTA processes
// units u = cta, cta+296, ... (< 4096); unit = (bx = u>>3, ko = u&7) = one
// offset of one 128-row M tile, K=256 as 4 chunks of 64. A and B chunks both
// staged (3 x 32KB). Fused BN+ReLU epilogue per unit; BN coeffs finalized
// in-kernel at the first epilogue after the PDL dependency sync.
// ============================================================================
#define CH_STAGE 32768                 // A 16K + B 16K
#define O_SC2    (3 * CH_STAGE)        // 98304
#define SMEM_P   (O_SC2 + 1024)        // 99328 (x2 CTA/SM fits easily)

__global__ __launch_bounds__(128, 2) void gemm_persist(float* __restrict__ out,
                                                       const float* __restrict__ gamma,
                                                       const float* __restrict__ beta)
{
    extern __shared__ char smem[];
    const uint32_t sb = smem_u32(smem);
    const int tid = threadIdx.x, lane = tid & 31, w = tid >> 5;
    const int wm = w & 1, wn = w >> 1;          // 2 x 2 warp grid, 64x64 tiles
    const int cta = blockIdx.x;
    float* scs = (float*)(smem + O_SC2);
    float* bis = scs + CO;

    const int nu = (NUNITS - 1 - cta) / NCTA + 1;   // 13 or 14 units
    const int nt = nu * 4;                           // chunks

    // chunk loader: t -> (unit, chunk); A chunk + B chunk (16KB each)
    auto load_t = [&](int t) {
        const int unit = cta + NCTA * (t >> 2), ck = t & 3;
        const int bx = unit >> 3, ko = unit & 7;
        const uint32_t dst = sb + (uint32_t)((t % 3) * CH_STAGE);
        const __half* asrc = g_xh + (size_t)bx * BM * KT + ck * 64;
        const __half* bsrc = g_wh + (size_t)ko * CO * KT + ck * 64;
#pragma unroll
        for (int j = 0; j < 16; j++) {
            int i = tid + 128 * j;                  // 0..2047
            int p = i >> 10, r = (i >> 3) & 127, kb = i & 7;
            const __half* src = (p ? bsrc : asrc) + (size_t)r * KT + kb * 8;
            cp16(dst + (uint32_t)(p * 16384 + r * 128 + (((kb ^ (r & 7))) << 4)), src);
        }
        CP_COMMIT();
    };
    load_t(0);
    if (nt > 1) load_t(1);

    float c[4][8][4];
#pragma unroll
    for (int mf = 0; mf < 4; mf++)
#pragma unroll
        for (int nt2 = 0; nt2 < 8; nt2++)
#pragma unroll
            for (int e = 0; e < 4; e++) c[mf][nt2][e] = 0.f;

    const int lrow = lane & 15, lcb = lane >> 4, xm = lane & 7;
    const uint32_t aRow = sb + (wm * 64 + lrow) * 128;
    const uint32_t bRow = sb + 16384 + (wn * 64 + lrow) * 128;
    bool have_stats = false;

    for (int t = 0; t < nt; t++) {
        if (t + 1 < nt) { CP_WAIT(1); } else { CP_WAIT(0); }
        __syncthreads();
        if (t + 2 < nt) load_t(t + 2);

        const uint32_t stageOff = (uint32_t)((t % 3) * CH_STAGE);
#pragma unroll
        for (int ks = 0; ks < 4; ks++) {
            const uint32_t xr = (uint32_t)(((ks * 2 + lcb) ^ xm) << 4);
            uint32_t af[4][4];
#pragma unroll
            for (int mf = 0; mf < 4; mf++) ldsm4(af[mf], aRow + stageOff + mf * 16 * 128 + xr);
            uint32_t bfr[8][2];
#pragma unroll
            for (int p = 0; p < 4; p++) {
                uint32_t r[4];
                ldsm4(r, bRow + stageOff + p * 16 * 128 + xr);
                bfr[2 * p][0] = r[0]; bfr[2 * p][1] = r[2];
                bfr[2 * p + 1][0] = r[1]; bfr[2 * p + 1][1] = r[3];
            }
#pragma unroll
            for (int mf = 0; mf < 4; mf++)
#pragma unroll
                for (int nt2 = 0; nt2 < 8; nt2++)
                    mma16816(c[mf][nt2], af[mf], bfr[nt2]);
        }

        if ((t & 3) == 3) {   // unit complete: fused BN + ReLU epilogue
            if (!have_stats) {
                cudaGridDependencySynchronize();  // stats_part complete
                float q = 0.f, m = 0.f;
#pragma unroll
                for (int k = 0; k < NOFF; k++) {
                    q += g_qpart[tid * NOFF + k];
                    m += g_mpart[tid * NOFF + k];
                }
                const float invN = 1.f / (float)((size_t)NOFF * MT);
                float mean = m * invN;
                float var  = q * invN - mean * mean;
                float sc   = gamma[tid] * rsqrtf(var + 1e-5f);
                scs[tid] = sc;
                bis[tid] = beta[tid] - mean * sc;
                have_stats = true;
                __syncthreads();
            }
            const int unit = cta + NCTA * (t >> 2);
            const int bx = unit >> 3, ko = unit & 7;
            const size_t rbase = (size_t)ko * MT + (size_t)bx * BM + wm * 64 + (lane >> 2);
            const int colb = wn * 64 + (lane & 3) * 2;
#pragma unroll
            for (int nt2 = 0; nt2 < 8; nt2++) {
                const int ch0 = colb + nt2 * 8;
                const float s0 = scs[ch0], s1 = scs[ch0 + 1];
                const float b0 = bis[ch0], b1 = bis[ch0 + 1];
#pragma unroll
                for (int mf = 0; mf < 4; mf++) {
                    float y0 = fmaxf(fmaf(c[mf][nt2][0], s0, b0), 0.f);
                    float y1 = fmaxf(fmaf(c[mf][nt2][1], s1, b1), 0.f);
                    float y2 = fmaxf(fmaf(c[mf][nt2][2], s0, b0), 0.f);
                    float y3 = fmaxf(fmaf(c[mf][nt2][3], s1, b1), 0.f);
                    float* p0 = out + (rbase + mf * 16) * CO + ch0;
                    *(float2*)p0 = make_float2(y0, y1);
                    *(float2*)(p0 + 8 * CO) = make_float2(y2, y3);
                }
            }
#pragma unroll
            for (int mf = 0; mf < 4; mf++)
#pragma unroll
                for (int nt2 = 0; nt2 < 8; nt2++)
#pragma unroll
                    for (int e = 0; e < 4; e++) c[mf][nt2][e] = 0.f;
        }
    }
}

// ============================================================================
extern "C" void kernel_launch(void* const* d_in, const int* in_sizes, int n_in,
                              void* d_out, int out_size)
{
    const float* x     = (const float*)d_in[0];   // [65536,256]
    const float* W     = (const float*)d_in[1];   // [8,256,128]
    const float* gamma = (const float*)d_in[2];
    const float* beta  = (const float*)d_in[3];
    float* out = (float*)d_out;

    cudaFuncSetAttribute(gram_k,       cudaFuncAttributeMaxDynamicSharedMemorySize, 2 * GP_STAGE);
    cudaFuncSetAttribute(gemm_persist, cudaFuncAttributeMaxDynamicSharedMemorySize, SMEM_P);

    convert_all<<<4096 + 256, 256>>>(x, W);
    dim3 ggrid(GSPLIT, GTILES);
    gram_k<<<ggrid, 128, 2 * GP_STAGE>>>();
    reduce_all<<<448, 256>>>();
    stats_part<<<CO * NOFF, 256>>>(W);

    // persistent gemm with PDL: prologue/mainloop overlap stats_part
    cudaLaunchConfig_t cfg = {};
    cfg.gridDim = dim3(NCTA);
    cfg.blockDim = dim3(128);
    cfg.dynamicSmemBytes = SMEM_P;
    cfg.stream = 0;
    cudaLaunchAttribute at[1];
    at[0].id = cudaLaunchAttributeProgrammaticStreamSerialization;
    at[0].val.programmaticStreamSerializationAllowed = 1;
    cfg.attrs = at;
    cfg.numAttrs = 1;
    cudaLaunchKernelEx(&cfg, gemm_persist, out, gamma, beta);
}